// round 5
// baseline (speedup 1.0000x reference)
#include <cuda_runtime.h>
#include <math.h>

#define PP 64
#define BB 2048
#define HH 128
#define NIN 2

constexpr int LDS_ = 132;   // padded smem row stride (floats) -> conflict-free ldmatrix
constexpr long ENC_SZ = (long)BB * PP * HH;       // 16777216
constexpr long HN_SZ  = (long)PP * 2 * BB * HH;   // 33554432
constexpr int  GY     = 37;                        // 4 * 37 = 148 CTAs = 1/SM

__device__ __forceinline__ float sigf(float x) { return 1.0f / (1.0f + expf(-x)); }

__device__ __forceinline__ unsigned sptr(const void* p) {
    return (unsigned)__cvta_generic_to_shared(p);
}
__device__ __forceinline__ void cp16(void* s, const void* g) {
    asm volatile("cp.async.cg.shared.global [%0], [%1], 16;\n" :: "r"(sptr(s)), "l"(g));
}
__device__ __forceinline__ void cp_commit() {
    asm volatile("cp.async.commit_group;\n" ::: "memory");
}
__device__ __forceinline__ void cp_wait1() {
    asm volatile("cp.async.wait_group 1;\n" ::: "memory");
}
__device__ __forceinline__ void cp_wait0() {
    asm volatile("cp.async.wait_group 0;\n" ::: "memory");
}
__device__ __forceinline__ void ldsm4(unsigned& r0, unsigned& r1, unsigned& r2, unsigned& r3,
                                      const void* p) {
    asm volatile("ldmatrix.sync.aligned.m8n8.x4.shared.b16 {%0,%1,%2,%3}, [%4];\n"
                 : "=r"(r0), "=r"(r1), "=r"(r2), "=r"(r3)
                 : "r"(sptr(p)));
}

// Persistent, W-resident, A-pipelined LSTM layer.
// Gate columns permuted (np = unit*4 + gate) so each CTA owns complete units.
template <int LAYER>
__global__ __launch_bounds__(LAYER == 0 ? 512 : 256, 1) void lstm_layer(
    const float* __restrict__ xin,
    const float* __restrict__ h0,
    const float* __restrict__ c0,
    const float* __restrict__ Wih0,
    const float* __restrict__ Whh0,
    const float* __restrict__ bih0,
    const float* __restrict__ bhh0,
    const float* __restrict__ Wih1,
    const float* __restrict__ Whh1,
    const float* __restrict__ bih1,
    const float* __restrict__ bhh1,
    float* __restrict__ dout)
{
    constexpr int NSRC    = (LAYER == 0) ? 1 : 2;
    constexpr int WM      = (LAYER == 0) ? 4 : 2;      // warps along M
    constexpr int THREADS = WM * 4 * 32;               // 4 warps along N always
    constexpr int MTL     = WM * 32;                   // CTA M-tile rows
    constexpr int MBLK_SH = (LAYER == 0) ? 4 : 5;      // m-blocks per pedestrian = 2048/MTL
    constexpr int TOTAL_MB = (PP * BB) / MTL;
    constexpr int WSTRIDE = 128 * LDS_;

    extern __shared__ float smem[];
    float* sW = smem;                         // [NSRC][128][132]
    float* sA = smem + NSRC * WSTRIDE;        // [2][MTL][132]

    const int tid  = threadIdx.x;
    const int lane = tid & 31;
    const int wid  = tid >> 5;
    const int grp  = lane >> 2;
    const int t4   = lane & 3;
    const int warpM = wid % WM;
    const int warpN = wid / WM;

    const int nb = blockIdx.x;                // units [nb*32, nb*32+32)
    const int by = blockIdx.y;

    const float* Wsrc[2];
    const float* bi;
    const float* bh;
    if (LAYER == 0) { Wsrc[0] = Whh0; Wsrc[1] = Whh0; bi = bih0; bh = bhh0; }
    else            { Wsrc[0] = Wih1; Wsrc[1] = Whh1; bi = bih1; bh = bhh1; }

    // ---- prologue: W tiles (resident for whole kernel) ----
    #pragma unroll
    for (int src = 0; src < NSRC; src++) {
        for (int it = 0; it < 4096 / THREADS; it++) {
            int idx = it * THREADS + tid;
            int np = idx >> 5, q = idx & 31;
            int norig = (np & 3) * HH + nb * 32 + (np >> 2);   // permuted gate rows
            cp16(sW + src * WSTRIDE + np * LDS_ + q * 4,
                 Wsrc[src] + (long)norig * HH + q * 4);
        }
    }

    const int nmb = (TOTAL_MB - by + GY - 1) / GY;
    const int S   = nmb * NSRC;

    // A-tile source pointer for a stage
    auto abase = [&](int sIdx) -> const float* {
        int src = sIdx % NSRC;
        int mb  = by + (sIdx / NSRC) * GY;
        int p   = mb >> MBLK_SH;
        int b0  = (mb & ((1 << MBLK_SH) - 1)) * MTL;
        if (LAYER == 0) return h0 + ((long)(p * 2) * BB + b0) * HH;
        if (src == 0)   return dout + ENC_SZ + ((long)(p * 2) * BB + b0) * HH;
        return h0 + ((long)(p * 2 + 1) * BB + b0) * HH;
    };
    auto load_a = [&](int sIdx) {
        const float* Ab = abase(sIdx);
        float* buf = sA + (sIdx & 1) * MTL * LDS_;
        #pragma unroll
        for (int it = 0; it < (MTL * 32) / THREADS; it++) {
            int idx = it * THREADS + tid;
            int row = idx >> 5, q = idx & 31;
            cp16(buf + row * LDS_ + q * 4, Ab + (long)row * HH + q * 4);
        }
    };

    load_a(0);
    cp_commit();                  // g0 = W + A0
    if (S > 1) load_a(1);
    cp_commit();                  // g1

    float* out_enc = dout;
    float* out_h   = dout + ENC_SZ;
    float* out_c   = dout + ENC_SZ + HN_SZ;

    float acc[2][4][4];

    for (int s = 0; s < S; s++) {
        cp_wait1();
        __syncthreads();          // A_s (and W) visible to all

        const int src = s % NSRC;
        const int mb  = by + (s / NSRC) * GY;
        const int p   = mb >> MBLK_SH;
        const int b0  = (mb & ((1 << MBLK_SH) - 1)) * MTL;
        float* bufc = sA + (s & 1) * MTL * LDS_;
        const float* sWs = sW + src * WSTRIDE;

        if (src == 0) {
            #pragma unroll
            for (int i = 0; i < 2; i++)
                #pragma unroll
                for (int j = 0; j < 4; j++)
                    #pragma unroll
                    for (int k = 0; k < 4; k++) acc[i][j][k] = 0.f;
        }

        // ---- mainloop: 16 k-steps ----
        #pragma unroll
        for (int k0 = 0; k0 < 16; k0++) {
            const int kk = k0 * 8;
            unsigned a[2][4];
            #pragma unroll
            for (int mt = 0; mt < 2; mt++) {
                const int R = warpM * 32 + mt * 16;
                const float* pa = bufc + (R + (lane & 15)) * LDS_ + kk + ((lane >> 4) << 2);
                ldsm4(a[mt][0], a[mt][1], a[mt][2], a[mt][3], pa);
            }
            unsigned b[2][4];
            #pragma unroll
            for (int nt2 = 0; nt2 < 2; nt2++) {
                const int C = warpN * 32 + nt2 * 16;
                const float* pb = sWs + (C + (lane & 7) + ((lane >> 4) << 3)) * LDS_
                                      + kk + (((lane >> 3) & 1) << 2);
                ldsm4(b[nt2][0], b[nt2][1], b[nt2][2], b[nt2][3], pb);
            }
            #pragma unroll
            for (int mt = 0; mt < 2; mt++) {
                #pragma unroll
                for (int nt = 0; nt < 4; nt++) {
                    const unsigned br0 = b[nt >> 1][(nt & 1) * 2];
                    const unsigned br1 = b[nt >> 1][(nt & 1) * 2 + 1];
                    asm volatile(
                        "mma.sync.aligned.m16n8k8.row.col.f32.tf32.tf32.f32 "
                        "{%0,%1,%2,%3}, {%4,%5,%6,%7}, {%8,%9}, {%0,%1,%2,%3};\n"
                        : "+f"(acc[mt][nt][0]), "+f"(acc[mt][nt][1]),
                          "+f"(acc[mt][nt][2]), "+f"(acc[mt][nt][3])
                        : "r"(a[mt][0]), "r"(a[mt][1]), "r"(a[mt][2]), "r"(a[mt][3]),
                          "r"(br0), "r"(br1));
                }
            }
        }

        if (src == NSRC - 1) {
            // ---- epilogue: stage gates into the just-consumed A buffer ----
            __syncthreads();
            #pragma unroll
            for (int mt = 0; mt < 2; mt++) {
                #pragma unroll
                for (int nt = 0; nt < 4; nt++) {
                    int r   = warpM * 32 + mt * 16 + grp;
                    int col = warpN * 32 + nt * 8 + t4 * 2;
                    bufc[r * LDS_ + col]           = acc[mt][nt][0];
                    bufc[r * LDS_ + col + 1]       = acc[mt][nt][1];
                    bufc[(r + 8) * LDS_ + col]     = acc[mt][nt][2];
                    bufc[(r + 8) * LDS_ + col + 1] = acc[mt][nt][3];
                }
            }
            __syncthreads();

            #pragma unroll
            for (int it = 0; it < (MTL * 32) / THREADS; it++) {
                int cell = it * THREADS + tid;       // MTL rows x 32 units
                int ml = cell >> 5, jl = cell & 31;
                int b = b0 + ml;
                int j = nb * 32 + jl;

                const float4 g4 = *(const float4*)(bufc + ml * LDS_ + jl * 4);
                float gi = g4.x + bi[j]          + bh[j];
                float gf = g4.y + bi[HH + j]     + bh[HH + j];
                float gg = g4.z + bi[2 * HH + j] + bh[2 * HH + j];
                float go = g4.w + bi[3 * HH + j] + bh[3 * HH + j];

                if (LAYER == 0) {
                    const float2 x2 = *(const float2*)(xin + ((long)b * PP + p) * NIN);
                    const float2 wi = *(const float2*)(Wih0 + (0 * HH + j) * NIN);
                    const float2 wf = *(const float2*)(Wih0 + (1 * HH + j) * NIN);
                    const float2 wg = *(const float2*)(Wih0 + (2 * HH + j) * NIN);
                    const float2 wo = *(const float2*)(Wih0 + (3 * HH + j) * NIN);
                    gi += x2.x * wi.x + x2.y * wi.y;
                    gf += x2.x * wf.x + x2.y * wf.y;
                    gg += x2.x * wg.x + x2.y * wg.y;
                    go += x2.x * wo.x + x2.y * wo.y;
                }

                const long sidx = ((long)(p * 2 + LAYER) * BB + b) * HH + j;
                const float cprev = c0[sidx];
                const float cn = sigf(gf) * cprev + sigf(gi) * tanhf(gg);
                const float hn = sigf(go) * tanhf(cn);

                out_h[sidx] = hn;
                out_c[sidx] = cn;
                if (LAYER == 1) out_enc[((long)b * PP + p) * HH + j] = hn;
            }
        }

        __syncthreads();          // everyone done with buf[s&1]
        if (s + 2 < S) load_a(s + 2);
        cp_commit();
    }
    cp_wait0();
}

extern "C" void kernel_launch(void* const* d_in, const int* in_sizes, int n_in,
                              void* d_out, int out_size)
{
    const float* xin  = (const float*)d_in[0];
    const float* h0   = (const float*)d_in[1];
    const float* c0   = (const float*)d_in[2];
    const float* Wih0 = (const float*)d_in[3];
    const float* Whh0 = (const float*)d_in[4];
    const float* bih0 = (const float*)d_in[5];
    const float* bhh0 = (const float*)d_in[6];
    const float* Wih1 = (const float*)d_in[7];
    const float* Whh1 = (const float*)d_in[8];
    const float* bih1 = (const float*)d_in[9];
    const float* bhh1 = (const float*)d_in[10];
    float* dout = (float*)d_out;

    // L0: W(1)*128*132 + A(2)*128*132 ; L1: W(2)*128*132 + A(2)*64*132  (both 202752 B)
    const int smem0 = (128 + 2 * 128) * LDS_ * (int)sizeof(float);
    const int smem1 = (2 * 128 + 2 * 64) * LDS_ * (int)sizeof(float);

    cudaFuncSetAttribute(lstm_layer<0>, cudaFuncAttributeMaxDynamicSharedMemorySize, smem0);
    cudaFuncSetAttribute(lstm_layer<1>, cudaFuncAttributeMaxDynamicSharedMemorySize, smem1);

    dim3 grid(4, GY);   // 148 CTAs: persistent, 1 per SM
    lstm_layer<0><<<grid, 512, smem0>>>(xin, h0, c0, Wih0, Whh0, bih0, bhh0,
                                        Wih1, Whh1, bih1, bhh1, dout);
    lstm_layer<1><<<grid, 256, smem1>>>(xin, h0, c0, Wih0, Whh0, bih0, bhh0,
                                        Wih1, Whh1, bih1, bhh1, dout);
}

// round 7
// speedup vs baseline: 1.3239x; 1.3239x over previous
#include <cuda_runtime.h>
#include <math.h>

#define PP 64
#define BB 2048
#define HH 128
#define NIN 2

constexpr long ENC_SZ = (long)BB * PP * HH;       // 16777216
constexpr long HN_SZ  = (long)PP * 2 * BB * HH;   // 33554432

constexpr int CH_STRIDE  = 36;                 // floats per row in chunk tiles (144B, ldsm conflict-free)
constexpr int TILE_FLTS  = 128 * CH_STRIDE;    // one A or W chunk tile = 4608 floats
constexpr int STG_STRIDE = 132;                // gate-staging stride

__device__ __forceinline__ float sigf(float x) { return 1.0f / (1.0f + expf(-x)); }

__device__ __forceinline__ unsigned sptr(const void* p) {
    return (unsigned)__cvta_generic_to_shared(p);
}
__device__ __forceinline__ void cp16(unsigned s, const void* g) {
    asm volatile("cp.async.cg.shared.global [%0], [%1], 16;\n" :: "r"(s), "l"(g));
}
__device__ __forceinline__ void cp_commit() {
    asm volatile("cp.async.commit_group;\n" ::: "memory");
}
__device__ __forceinline__ void ldsm4(unsigned& r0, unsigned& r1, unsigned& r2, unsigned& r3,
                                      const void* p) {
    asm volatile("ldmatrix.sync.aligned.m8n8.x4.shared.b16 {%0,%1,%2,%3}, [%4];\n"
                 : "=r"(r0), "=r"(r1), "=r"(r2), "=r"(r3)
                 : "r"(sptr(p)));
}

// LSTM layer: TF32 mma.sync GEMM with K-chunked double-buffered cp.async pipeline,
// m64xn32 warp tiles, fused cell epilogue. Gate columns permuted (np = unit*4+gate)
// so each CTA's 128 columns are 32 complete units.
template <int LAYER>
__global__ __launch_bounds__(256, 2) void lstm_layer(
    const float* __restrict__ xin,
    const float* __restrict__ h0,
    const float* __restrict__ c0,
    const float* __restrict__ Wih0,
    const float* __restrict__ Whh0,
    const float* __restrict__ bih0,
    const float* __restrict__ bhh0,
    const float* __restrict__ Wih1,
    const float* __restrict__ Whh1,
    const float* __restrict__ bih1,
    const float* __restrict__ bhh1,
    float* __restrict__ dout)
{
    constexpr int NC = (LAYER == 0) ? 4 : 8;   // 32-wide K chunks (K=128 or 256)

    extern __shared__ float smem[];
    float* bsum   = smem;            // 128 permuted bias sums
    float* chunks = smem + 128;      // 2 buffers x (A tile + W tile)

    const int tid  = threadIdx.x;
    const int lane = tid & 31;
    const int wid  = tid >> 5;
    const int grp  = lane >> 2;
    const int t4   = lane & 3;
    const int warpM = wid & 1;       // 2 warps along M: m64 each
    const int warpN = wid >> 1;      // 4 warps along N: n32 each

    const int nb = blockIdx.x;       // units [nb*32, nb*32+32)
    const int mb = blockIdx.y;       // 1024 m-blocks of 128 rows
    const int p  = mb >> 4;
    const int b0 = (mb & 15) * 128;

    const float* bi = LAYER ? bih1 : bih0;
    const float* bh = LAYER ? bhh1 : bhh0;
    if (tid < 128) {
        int g = tid & 3, u = tid >> 2, j = nb * 32 + u;
        bsum[tid] = bi[g * HH + j] + bh[g * HH + j];
    }

    float acc[4][4][4];
    #pragma unroll
    for (int i = 0; i < 4; i++)
        #pragma unroll
        for (int j = 0; j < 4; j++)
            #pragma unroll
            for (int k = 0; k < 4; k++) acc[i][j][k] = 0.f;

    auto load_chunk = [&](int c) {
        const int src = (LAYER == 1 && c >= 4) ? 1 : 0;
        const int kk  = (c & 3) * 32;
        const float* Ab;
        const float* Ws;
        if (LAYER == 0) {
            Ab = h0 + ((long)(p * 2) * BB + b0) * HH;
            Ws = Whh0;
        } else if (src == 0) {
            Ab = dout + ENC_SZ + ((long)(p * 2) * BB + b0) * HH;   // h1 from layer-0
            Ws = Wih1;
        } else {
            Ab = h0 + ((long)(p * 2 + 1) * BB + b0) * HH;
            Ws = Whh1;
        }
        float* buf = chunks + (c & 1) * 2 * TILE_FLTS;
        // A chunk: 128 rows x 32 k
        #pragma unroll
        for (int it = 0; it < 4; it++) {
            int idx = it * 256 + tid;
            int row = idx >> 3, q = idx & 7;
            cp16(sptr(buf + row * CH_STRIDE + q * 4), Ab + (long)row * HH + kk + q * 4);
        }
        // W chunk: 128 permuted gate-cols x 32 k
        #pragma unroll
        for (int it = 0; it < 4; it++) {
            int idx = it * 256 + tid;
            int np = idx >> 3, q = idx & 7;
            int norig = (np & 3) * HH + nb * 32 + (np >> 2);
            cp16(sptr(buf + TILE_FLTS + np * CH_STRIDE + q * 4),
                 Ws + (long)norig * HH + kk + q * 4);
        }
        cp_commit();
    };

    load_chunk(0);

    for (int c = 0; c < NC; c++) {
        if (c + 1 < NC) load_chunk(c + 1);
        if (c + 1 < NC) asm volatile("cp.async.wait_group 1;" ::: "memory");
        else            asm volatile("cp.async.wait_group 0;" ::: "memory");
        __syncthreads();

        const float* Ab = chunks + (c & 1) * 2 * TILE_FLTS;
        const float* Wb = Ab + TILE_FLTS;

        #pragma unroll
        for (int ks = 0; ks < 4; ks++) {
            const int kk = ks * 8;
            unsigned a[4][4];
            #pragma unroll
            for (int mt = 0; mt < 4; mt++) {
                const int R = warpM * 64 + mt * 16;
                const float* pa = Ab + (R + (lane & 15)) * CH_STRIDE + kk + ((lane >> 4) << 2);
                ldsm4(a[mt][0], a[mt][1], a[mt][2], a[mt][3], pa);
            }
            unsigned b[2][4];
            #pragma unroll
            for (int nt2 = 0; nt2 < 2; nt2++) {
                const int C = warpN * 32 + nt2 * 16;
                const float* pb = Wb + (C + (lane & 7) + ((lane >> 4) << 3)) * CH_STRIDE
                                     + kk + (((lane >> 3) & 1) << 2);
                ldsm4(b[nt2][0], b[nt2][1], b[nt2][2], b[nt2][3], pb);
            }
            #pragma unroll
            for (int mt = 0; mt < 4; mt++) {
                #pragma unroll
                for (int nt = 0; nt < 4; nt++) {
                    const unsigned br0 = b[nt >> 1][(nt & 1) * 2];
                    const unsigned br1 = b[nt >> 1][(nt & 1) * 2 + 1];
                    asm volatile(
                        "mma.sync.aligned.m16n8k8.row.col.f32.tf32.tf32.f32 "
                        "{%0,%1,%2,%3}, {%4,%5,%6,%7}, {%8,%9}, {%0,%1,%2,%3};\n"
                        : "+f"(acc[mt][nt][0]), "+f"(acc[mt][nt][1]),
                          "+f"(acc[mt][nt][2]), "+f"(acc[mt][nt][3])
                        : "r"(a[mt][0]), "r"(a[mt][1]), "r"(a[mt][2]), "r"(a[mt][3]),
                          "r"(br0), "r"(br1));
                }
            }
        }
        __syncthreads();   // buf[c&1] free for load(c+2)
    }

    // ---- stage gates into the (dead) chunk buffers, stride 132 ----
    float* sG = chunks;
    #pragma unroll
    for (int mt = 0; mt < 4; mt++) {
        #pragma unroll
        for (int nt = 0; nt < 4; nt++) {
            int r   = warpM * 64 + mt * 16 + grp;
            int col = warpN * 32 + nt * 8 + t4 * 2;
            sG[r * STG_STRIDE + col]           = acc[mt][nt][0];
            sG[r * STG_STRIDE + col + 1]       = acc[mt][nt][1];
            sG[(r + 8) * STG_STRIDE + col]     = acc[mt][nt][2];
            sG[(r + 8) * STG_STRIDE + col + 1] = acc[mt][nt][3];
        }
    }
    __syncthreads();

    // ---- fused LSTM cell epilogue ----
    float* out_enc = dout;
    float* out_h   = dout + ENC_SZ;
    float* out_c   = dout + ENC_SZ + HN_SZ;

    #pragma unroll
    for (int it = 0; it < 16; it++) {
        int cell = it * 256 + tid;        // 128 rows x 32 units
        int ml = cell >> 5, jl = cell & 31;
        int b = b0 + ml;
        int j = nb * 32 + jl;

        const float4 g4 = *(const float4*)(sG + ml * STG_STRIDE + jl * 4);
        const float4 bs = *(const float4*)(bsum + jl * 4);
        float gi = g4.x + bs.x;
        float gf = g4.y + bs.y;
        float gg = g4.z + bs.z;
        float go = g4.w + bs.w;

        if (LAYER == 0) {
            const float2 x2 = *(const float2*)(xin + ((long)b * PP + p) * NIN);
            const float2 wi = *(const float2*)(Wih0 + (0 * HH + j) * NIN);
            const float2 wf = *(const float2*)(Wih0 + (1 * HH + j) * NIN);
            const float2 wg = *(const float2*)(Wih0 + (2 * HH + j) * NIN);
            const float2 wo = *(const float2*)(Wih0 + (3 * HH + j) * NIN);
            gi += x2.x * wi.x + x2.y * wi.y;
            gf += x2.x * wf.x + x2.y * wf.y;
            gg += x2.x * wg.x + x2.y * wg.y;
            go += x2.x * wo.x + x2.y * wo.y;
        }

        const long sidx = ((long)(p * 2 + LAYER) * BB + b) * HH + j;
        const float cprev = c0[sidx];
        const float cn = sigf(gf) * cprev + sigf(gi) * tanhf(gg);
        const float hn = sigf(go) * tanhf(cn);

        out_h[sidx] = hn;
        out_c[sidx] = cn;
        if (LAYER == 1) out_enc[((long)b * PP + p) * HH + j] = hn;
    }
}

extern "C" void kernel_launch(void* const* d_in, const int* in_sizes, int n_in,
                              void* d_out, int out_size)
{
    const float* xin  = (const float*)d_in[0];
    const float* h0   = (const float*)d_in[1];
    const float* c0   = (const float*)d_in[2];
    const float* Wih0 = (const float*)d_in[3];
    const float* Whh0 = (const float*)d_in[4];
    const float* bih0 = (const float*)d_in[5];
    const float* bhh0 = (const float*)d_in[6];
    const float* Wih1 = (const float*)d_in[7];
    const float* Whh1 = (const float*)d_in[8];
    const float* bih1 = (const float*)d_in[9];
    const float* bhh1 = (const float*)d_in[10];
    float* dout = (float*)d_out;

    const int smem_bytes = (128 + 4 * TILE_FLTS) * (int)sizeof(float);  // 74240

    cudaFuncSetAttribute(lstm_layer<0>, cudaFuncAttributeMaxDynamicSharedMemorySize, smem_bytes);
    cudaFuncSetAttribute(lstm_layer<1>, cudaFuncAttributeMaxDynamicSharedMemorySize, smem_bytes);

    dim3 grid(4, 1024);   // 4 n-blocks x 1024 m-blocks
    lstm_layer<0><<<grid, 256, smem_bytes>>>(xin, h0, c0, Wih0, Whh0, bih0, bhh0,
                                             Wih1, Whh1, bih1, bhh1, dout);
    lstm_layer<1><<<grid, 256, smem_bytes>>>(xin, h0, c0, Wih0, Whh0, bih0, bhh0,
                                             Wih1, Whh1, bih1, bhh1, dout);
}

// round 8
// speedup vs baseline: 2.3759x; 1.7947x over previous
#include <cuda_runtime.h>
#include <cuda_fp16.h>
#include <math.h>

#define PP 64
#define BB 2048
#define HH 128
#define NIN 2

constexpr long ENC_SZ = (long)BB * PP * HH;       // 16777216
constexpr long HN_SZ  = (long)PP * 2 * BB * HH;   // 33554432

constexpr int CHS        = 72;                 // halfs per row in chunk tiles (144B, ldsm conflict-free)
constexpr int TILE_H     = 128 * CHS;          // one chunk tile = 9216 halfs = 18432 B
constexpr int STG_STRIDE = 132;                // fp32 gate-staging stride

// fp16 scratch (static device arrays -- allocation-free per harness rules)
__device__ __half g_h0h[(long)PP * 2 * BB * HH];   // h0 both layers, fp16
__device__ __half g_h1h[(long)PP * BB * HH];       // layer-0 output h1, fp16
__device__ __half g_w0[512 * 128];                 // permuted Whh0
__device__ __half g_w1[512 * 256];                 // permuted [Wih1 | Whh1]

__device__ __forceinline__ float tanha(float x) {
    float y; asm("tanh.approx.f32 %0, %1;" : "=f"(y) : "f"(x)); return y;
}
__device__ __forceinline__ float sigf(float x) { return 0.5f * tanha(0.5f * x) + 0.5f; }

__device__ __forceinline__ unsigned sptr(const void* p) {
    return (unsigned)__cvta_generic_to_shared(p);
}
__device__ __forceinline__ void cp16(unsigned s, const void* g) {
    asm volatile("cp.async.cg.shared.global [%0], [%1], 16;\n" :: "r"(s), "l"(g));
}
__device__ __forceinline__ void cp_commit() {
    asm volatile("cp.async.commit_group;\n" ::: "memory");
}
__device__ __forceinline__ void ldsm4(unsigned& r0, unsigned& r1, unsigned& r2, unsigned& r3,
                                      const void* p) {
    asm volatile("ldmatrix.sync.aligned.m8n8.x4.shared.b16 {%0,%1,%2,%3}, [%4];\n"
                 : "=r"(r0), "=r"(r1), "=r"(r2), "=r"(r3)
                 : "r"(sptr(p)));
}

// ---- pre-pass: fp32 -> fp16 conversions (h0 full, W permuted) ----
__global__ __launch_bounds__(256) void prep(
    const float* __restrict__ h0,
    const float* __restrict__ Whh0,
    const float* __restrict__ Wih1,
    const float* __restrict__ Whh1)
{
    const long stride = (long)gridDim.x * blockDim.x;
    const long tid = (long)blockIdx.x * blockDim.x + threadIdx.x;

    const long n4 = (long)PP * 2 * BB * HH / 4;
    for (long i = tid; i < n4; i += stride) {
        float4 v = ((const float4*)h0)[i];
        ((__half2*)g_h0h)[2 * i]     = __floats2half2_rn(v.x, v.y);
        ((__half2*)g_h0h)[2 * i + 1] = __floats2half2_rn(v.z, v.w);
    }
    for (long i = tid; i < 512 * 128; i += stride) {
        int pr = (int)(i >> 7), k = (int)(i & 127);
        int nb = pr >> 7, np = pr & 127;
        int norig = (np & 3) * 128 + nb * 32 + (np >> 2);
        g_w0[i] = __float2half_rn(Whh0[norig * 128 + k]);
    }
    for (long i = tid; i < 512 * 256; i += stride) {
        int pr = (int)(i >> 8), k = (int)(i & 255);
        int nb = pr >> 7, np = pr & 127;
        int norig = (np & 3) * 128 + nb * 32 + (np >> 2);
        float v = (k < 128) ? Wih1[norig * 128 + k] : Whh1[norig * 128 + (k - 128)];
        g_w1[i] = __float2half_rn(v);
    }
}

// LSTM layer: fp16 mma.sync m16n8k16 GEMM, K=64 double-buffered cp.async chunks,
// m64xn32 warp tiles, fused cell epilogue. Gate columns permuted (np = unit*4+gate).
template <int LAYER>
__global__ __launch_bounds__(256, 2) void lstm_layer(
    const float* __restrict__ xin,
    const float* __restrict__ c0,
    const float* __restrict__ Wih0,
    const float* __restrict__ bih0,
    const float* __restrict__ bhh0,
    const float* __restrict__ bih1,
    const float* __restrict__ bhh1,
    float* __restrict__ dout)
{
    constexpr int NC = (LAYER == 0) ? 2 : 4;   // 64-wide K chunks (K=128 or 256)
    constexpr int KT = (LAYER == 0) ? 128 : 256;

    extern __shared__ __align__(16) unsigned char smem_raw[];
    float*  bsum   = (float*)smem_raw;                    // 128 permuted bias sums
    __half* chunks = (__half*)(smem_raw + 512);           // 2 buf x (A tile + W tile)

    const int tid  = threadIdx.x;
    const int lane = tid & 31;
    const int wid  = tid >> 5;
    const int grp  = lane >> 2;
    const int t4   = lane & 3;
    const int warpM = wid & 1;       // 2 warps along M: m64 each
    const int warpN = wid >> 1;      // 4 warps along N: n32 each

    const int nb = blockIdx.x;       // units [nb*32, nb*32+32)
    const int mb = blockIdx.y;       // 1024 m-blocks of 128 rows
    const int p  = mb >> 4;
    const int b0 = (mb & 15) * 128;

    const float* bi = LAYER ? bih1 : bih0;
    const float* bh = LAYER ? bhh1 : bhh0;
    if (tid < 128) {
        int g = tid & 3, u = tid >> 2, j = nb * 32 + u;
        bsum[tid] = bi[g * HH + j] + bh[g * HH + j];
    }

    float acc[4][4][4];
    #pragma unroll
    for (int i = 0; i < 4; i++)
        #pragma unroll
        for (int j = 0; j < 4; j++)
            #pragma unroll
            for (int k = 0; k < 4; k++) acc[i][j][k] = 0.f;

    const __half* gw = LAYER ? g_w1 : g_w0;

    auto load_chunk = [&](int c) {
        const __half* Ah;
        int kkA;
        if (LAYER == 0) {
            Ah = g_h0h + ((long)(p * 2) * BB + b0) * HH;  kkA = c * 64;
        } else if (c < 2) {
            Ah = g_h1h + ((long)p * BB + b0) * HH;        kkA = c * 64;
        } else {
            Ah = g_h0h + ((long)(p * 2 + 1) * BB + b0) * HH; kkA = (c - 2) * 64;
        }
        const int kkW = c * 64;
        __half* buf = chunks + (c & 1) * 2 * TILE_H;
        // A chunk: 128 rows x 64 k (8 x 16B per row)
        #pragma unroll
        for (int it = 0; it < 4; it++) {
            int idx = it * 256 + tid;
            int row = idx >> 3, q = idx & 7;
            cp16(sptr(buf + row * CHS + q * 8), Ah + (long)row * HH + kkA + q * 8);
        }
        // W chunk: 128 permuted gate-cols x 64 k
        #pragma unroll
        for (int it = 0; it < 4; it++) {
            int idx = it * 256 + tid;
            int np = idx >> 3, q = idx & 7;
            cp16(sptr(buf + TILE_H + np * CHS + q * 8),
                 gw + (long)(nb * 128 + np) * KT + kkW + q * 8);
        }
        cp_commit();
    };

    load_chunk(0);

    for (int c = 0; c < NC; c++) {
        if (c + 1 < NC) load_chunk(c + 1);
        if (c + 1 < NC) asm volatile("cp.async.wait_group 1;" ::: "memory");
        else            asm volatile("cp.async.wait_group 0;" ::: "memory");
        __syncthreads();

        const __half* Ab = chunks + (c & 1) * 2 * TILE_H;
        const __half* Wb = Ab + TILE_H;

        #pragma unroll
        for (int ks = 0; ks < 4; ks++) {
            const int kk = ks * 16;
            unsigned a[4][4];
            #pragma unroll
            for (int mt = 0; mt < 4; mt++) {
                const int R = warpM * 64 + mt * 16;
                const __half* pa = Ab + (R + (lane & 15)) * CHS + kk + ((lane >> 4) << 3);
                ldsm4(a[mt][0], a[mt][1], a[mt][2], a[mt][3], pa);
            }
            // B: two x4 loads -> b0 (k0-7) and b1 (k8-15) for the 4 n8 groups
            unsigned b0[4], b1[4];
            {
                const int C = warpN * 32;
                const __half* pb0 = Wb + (C + lane) * CHS + kk;
                ldsm4(b0[0], b0[1], b0[2], b0[3], pb0);
                const __half* pb1 = Wb + (C + lane) * CHS + kk + 8;
                ldsm4(b1[0], b1[1], b1[2], b1[3], pb1);
            }
            #pragma unroll
            for (int mt = 0; mt < 4; mt++) {
                #pragma unroll
                for (int nt = 0; nt < 4; nt++) {
                    asm volatile(
                        "mma.sync.aligned.m16n8k16.row.col.f32.f16.f16.f32 "
                        "{%0,%1,%2,%3}, {%4,%5,%6,%7}, {%8,%9}, {%0,%1,%2,%3};\n"
                        : "+f"(acc[mt][nt][0]), "+f"(acc[mt][nt][1]),
                          "+f"(acc[mt][nt][2]), "+f"(acc[mt][nt][3])
                        : "r"(a[mt][0]), "r"(a[mt][1]), "r"(a[mt][2]), "r"(a[mt][3]),
                          "r"(b0[nt]), "r"(b1[nt]));
                }
            }
        }
        __syncthreads();   // buf[c&1] free for load(c+2)
    }

    // ---- stage gates (fp32) into the dead chunk buffers ----
    float* sG = (float*)chunks;
    #pragma unroll
    for (int mt = 0; mt < 4; mt++) {
        #pragma unroll
        for (int nt = 0; nt < 4; nt++) {
            int r   = warpM * 64 + mt * 16 + grp;
            int col = warpN * 32 + nt * 8 + t4 * 2;
            sG[r * STG_STRIDE + col]           = acc[mt][nt][0];
            sG[r * STG_STRIDE + col + 1]       = acc[mt][nt][1];
            sG[(r + 8) * STG_STRIDE + col]     = acc[mt][nt][2];
            sG[(r + 8) * STG_STRIDE + col + 1] = acc[mt][nt][3];
        }
    }
    __syncthreads();

    // ---- fused LSTM cell epilogue ----
    float* out_enc = dout;
    float* out_h   = dout + ENC_SZ;
    float* out_c   = dout + ENC_SZ + HN_SZ;

    #pragma unroll
    for (int it = 0; it < 16; it++) {
        int cell = it * 256 + tid;        // 128 rows x 32 units
        int ml = cell >> 5, jl = cell & 31;
        int b = b0 + ml;
        int j = nb * 32 + jl;

        const float4 g4 = *(const float4*)(sG + ml * STG_STRIDE + jl * 4);
        const float4 bs = *(const float4*)(bsum + jl * 4);
        float gi = g4.x + bs.x;
        float gf = g4.y + bs.y;
        float gg = g4.z + bs.z;
        float go = g4.w + bs.w;

        if (LAYER == 0) {
            const float2 x2 = *(const float2*)(xin + ((long)b * PP + p) * NIN);
            const float2 wi = *(const float2*)(Wih0 + (0 * HH + j) * NIN);
            const float2 wf = *(const float2*)(Wih0 + (1 * HH + j) * NIN);
            const float2 wg = *(const float2*)(Wih0 + (2 * HH + j) * NIN);
            const float2 wo = *(const float2*)(Wih0 + (3 * HH + j) * NIN);
            gi += x2.x * wi.x + x2.y * wi.y;
            gf += x2.x * wf.x + x2.y * wf.y;
            gg += x2.x * wg.x + x2.y * wg.y;
            go += x2.x * wo.x + x2.y * wo.y;
        }

        const long sidx = ((long)(p * 2 + LAYER) * BB + b) * HH + j;
        const float cprev = c0[sidx];
        const float cn = sigf(gf) * cprev + sigf(gi) * tanha(gg);
        const float hn = sigf(go) * tanha(cn);

        out_h[sidx] = hn;
        out_c[sidx] = cn;
        if (LAYER == 0) {
            g_h1h[((long)p * BB + b) * HH + j] = __float2half_rn(hn);
        } else {
            out_enc[((long)b * PP + p) * HH + j] = hn;
        }
    }
}

extern "C" void kernel_launch(void* const* d_in, const int* in_sizes, int n_in,
                              void* d_out, int out_size)
{
    const float* xin  = (const float*)d_in[0];
    const float* h0   = (const float*)d_in[1];
    const float* c0   = (const float*)d_in[2];
    const float* Wih0 = (const float*)d_in[3];
    const float* Whh0 = (const float*)d_in[4];
    const float* bih0 = (const float*)d_in[5];
    const float* bhh0 = (const float*)d_in[6];
    const float* Wih1 = (const float*)d_in[7];
    const float* Whh1 = (const float*)d_in[8];
    const float* bih1 = (const float*)d_in[9];
    const float* bhh1 = (const float*)d_in[10];
    float* dout = (float*)d_out;

    // smem: 512B bias + 4 tiles x 18432B = 74240B total -> 2 CTAs/SM
    const int smem_bytes = 512 + 4 * TILE_H * (int)sizeof(__half);

    cudaFuncSetAttribute(lstm_layer<0>, cudaFuncAttributeMaxDynamicSharedMemorySize, smem_bytes);
    cudaFuncSetAttribute(lstm_layer<1>, cudaFuncAttributeMaxDynamicSharedMemorySize, smem_bytes);

    prep<<<1024, 256>>>(h0, Whh0, Wih1, Whh1);

    dim3 grid(4, 1024);   // 4 n-blocks x 1024 m-blocks
    lstm_layer<0><<<grid, 256, smem_bytes>>>(xin, c0, Wih0, bih0, bhh0, bih1, bhh1, dout);
    lstm_layer<1><<<grid, 256, smem_bytes>>>(xin, c0, Wih0, bih0, bhh0, bih1, bhh1, dout);
}